// round 8
// baseline (speedup 1.0000x reference)
#include <cuda_runtime.h>

#define H 2048
#define S 8192

// Scratch (no allocs allowed). g_u starts zero (static init); k_finalize
// re-zeros it each invocation, so "g_u == 0 on entry" holds on every call.
__device__ float g_u[H];
__device__ float g_energy[S];
__device__ float g_mb[S / 16];    // per-energy-block local max   (512)
__device__ float g_zb[S / 16];    // per-energy-block exp-sum     (512)

// ---------------------------------------------------------------------------
// Kernel 1: u GEMV, float4 columns. Each thread owns 4 adjacent columns and a
// 16-row i-chunk, fully unrolled -> 16 x 128-bit W loads in flight.
// Grid (H/(256*4), 128) = (2, 128) = 256 blocks. Coalesced 128-bit on j.
// ---------------------------------------------------------------------------
#define ICHUNKS 128
#define IROWS   (H / ICHUNKS)     // 16

__global__ void k_compute_u(const float* __restrict__ h,
                            const float* __restrict__ W) {
    const int j4 = blockIdx.x * blockDim.x + threadIdx.x;   // float4 column
    const int i0 = blockIdx.y * IROWS;
    const float4* W4 = reinterpret_cast<const float4*>(W);

    float4 acc = make_float4(0.f, 0.f, 0.f, 0.f);
#pragma unroll
    for (int r = 0; r < IROWS; ++r) {
        const int i = i0 + r;
        const float hv = __ldg(h + i);
        const float4 w = W4[(size_t)i * (H / 4) + j4];
        acc.x = fmaf(hv, w.x, acc.x);
        acc.y = fmaf(hv, w.y, acc.y);
        acc.z = fmaf(hv, w.z, acc.z);
        acc.w = fmaf(hv, w.w, acc.w);
    }
    float* dst = &g_u[j4 * 4];
    atomicAdd(dst + 0, acc.x);
    atomicAdd(dst + 1, acc.y);
    atomicAdd(dst + 2, acc.z);
    atomicAdd(dst + 3, acc.w);
}

// ---------------------------------------------------------------------------
// Kernel 2: energy[s] = enc[s,:] . u  — one warp per row, 16 rows per
// 512-thread block. u staged in smem once per block (kills the per-warp
// global u stream and ~halves register pressure so all 16 enc float4 loads
// stay in flight). Each block emits (m_b, z_b).
// ---------------------------------------------------------------------------
__global__ __launch_bounds__(512)
void k_energy(const float* __restrict__ enc) {
    __shared__ float4 sU[H / 4];   // 8 KB
    __shared__ float  sE[16];

    const int tid  = threadIdx.x;
    const int wid  = tid >> 5;     // 0..15
    const int lane = tid & 31;
    const int s    = blockIdx.x * 16 + wid;

    // Stage u (512 float4, 512 threads -> one each).
    sU[tid] = reinterpret_cast<const float4*>(g_u)[tid];
    __syncthreads();

    const float4* row = reinterpret_cast<const float4*>(enc + (size_t)s * H);

    float acc = 0.0f;
#pragma unroll
    for (int k = 0; k < (H / 4) / 32; ++k) {   // 16 iterations
        float4 v = row[lane + k * 32];
        float4 u = sU [lane + k * 32];
        acc = fmaf(v.x, u.x, acc);
        acc = fmaf(v.y, u.y, acc);
        acc = fmaf(v.z, u.z, acc);
        acc = fmaf(v.w, u.w, acc);
    }
#pragma unroll
    for (int off = 16; off; off >>= 1)
        acc += __shfl_xor_sync(0xFFFFFFFFu, acc, off);

    if (lane == 0) {
        g_energy[s] = acc;
        sE[wid] = acc;
    }
    __syncthreads();

    if (wid == 0) {
        float e = (lane < 16) ? sE[lane] : -1e30f;
        float m = e;
#pragma unroll
        for (int off = 16; off; off >>= 1)
            m = fmaxf(m, __shfl_xor_sync(0xFFFFFFFFu, m, off));
        float z = (lane < 16) ? __expf(e - m) : 0.0f;
#pragma unroll
        for (int off = 16; off; off >>= 1)
            z += __shfl_xor_sync(0xFFFFFFFFu, z, off);
        if (lane == 0) { g_mb[blockIdx.x] = m; g_zb[blockIdx.x] = z; }
    }
}

// ---------------------------------------------------------------------------
// Kernel 3: finalize. 32 blocks x 256 threads. Every block redundantly
// reduces the 512 (m,z) pairs (L2-hot) to (M, 1/Z), then normalizes its own
// 256-row output slice. Blocks 0..7 also re-zero g_u.
// ---------------------------------------------------------------------------
__global__ void k_finalize(float* __restrict__ out) {
    __shared__ float red[8];
    __shared__ float sM, sInvZ;

    const int tid  = threadIdx.x;     // 0..255
    const int lane = tid & 31;
    const int wid  = tid >> 5;        // 0..7

    float m0[2], z0[2];
#pragma unroll
    for (int k = 0; k < 2; ++k) {
        m0[k] = g_mb[tid + k * 256];
        z0[k] = g_zb[tid + k * 256];
    }

    // ---- block max ----
    float m = fmaxf(m0[0], m0[1]);
#pragma unroll
    for (int off = 16; off; off >>= 1)
        m = fmaxf(m, __shfl_xor_sync(0xFFFFFFFFu, m, off));
    if (lane == 0) red[wid] = m;
    __syncthreads();
    if (tid < 8) {
        float v = red[tid];
#pragma unroll
        for (int off = 4; off; off >>= 1)
            v = fmaxf(v, __shfl_xor_sync(0xFFu, v, off));
        if (tid == 0) sM = v;
    }
    __syncthreads();
    const float M = sM;

    // ---- block sum of z_i * exp(m_i - M) ----
    float z = 0.0f;
#pragma unroll
    for (int k = 0; k < 2; ++k) z += z0[k] * __expf(m0[k] - M);
#pragma unroll
    for (int off = 16; off; off >>= 1)
        z += __shfl_xor_sync(0xFFFFFFFFu, z, off);
    if (lane == 0) red[wid] = z;
    __syncthreads();
    if (tid < 8) {
        float v = red[tid];
#pragma unroll
        for (int off = 4; off; off >>= 1)
            v += __shfl_xor_sync(0xFFu, v, off);
        if (tid == 0) sInvZ = 1.0f / v;
    }
    __syncthreads();
    const float invZ = sInvZ;

    // ---- normalize this block's slice ----
    const int s = blockIdx.x * 256 + tid;
    out[s] = __expf(g_energy[s] - M) * invZ;

    // ---- restore g_u == 0 invariant for the next invocation ----
    if (blockIdx.x < 8)
        g_u[blockIdx.x * 256 + tid] = 0.0f;
}

// ---------------------------------------------------------------------------
// Launch. Inputs: hidden[2048], encoder_outputs[8192*2048], W[2048*2048],
// b[2048] (zero + softmax-invariant -> ignored). Output: 8192 floats.
// ---------------------------------------------------------------------------
extern "C" void kernel_launch(void* const* d_in, const int* in_sizes, int n_in,
                              void* d_out, int out_size) {
    const float* hidden = (const float*)d_in[0];
    const float* enc    = (const float*)d_in[1];
    const float* W      = (const float*)d_in[2];
    float* out          = (float*)d_out;

    dim3 g1(H / (256 * 4), ICHUNKS);   // (2, 128)
    k_compute_u<<<g1, 256>>>(hidden, W);

    k_energy<<<S / 16, 512>>>(enc);

    k_finalize<<<S / 256, 256>>>(out);
}

// round 9
// speedup vs baseline: 1.3949x; 1.3949x over previous
#include <cuda_runtime.h>

#define H 2048
#define S 8192

// Scratch (no allocs allowed). g_u starts zero (static init); k_finalize
// re-zeros it each invocation, so "g_u == 0 on entry" holds on every call.
__device__ float g_u[H];
__device__ float g_energy[S];
__device__ float g_mb[256];       // per-energy-block local max
__device__ float g_zb[256];       // per-energy-block exp-sum

// ---------------------------------------------------------------------------
// Kernel 1: u[j] += sum over a 16-row i-chunk of h[i] * W[i, j]
// Grid (H/256, 128) = 1024 blocks (~7/SM). Fully unrolled 16-row loop,
// scalar coalesced loads -> maximal chip-wide loads in flight.
// ---------------------------------------------------------------------------
#define ICHUNKS 128
#define IROWS   (H / ICHUNKS)     // 16

__global__ void k_compute_u(const float* __restrict__ h,
                            const float* __restrict__ W) {
    const int j  = blockIdx.x * blockDim.x + threadIdx.x;
    const int i0 = blockIdx.y * IROWS;

    float acc = 0.0f;
#pragma unroll
    for (int r = 0; r < IROWS; ++r) {
        const int i = i0 + r;
        acc = fmaf(__ldg(h + i), W[(size_t)i * H + j], acc);
    }
    atomicAdd(&g_u[j], acc);
}

// ---------------------------------------------------------------------------
// Kernel 2: energy[s] = enc[s,:] . u — u REGISTER-RESIDENT per warp.
// Each lane caches u4[lane + 32k] (k=0..15, 64 regs), then the warp streams
// 4 rows of enc (16 independent LDG.128 per row). u global traffic drops
// from 64MB to 2MB. 256 blocks x 8 warps x 4 rows = 8192 rows.
// ---------------------------------------------------------------------------
#define RPW 4

__global__ __launch_bounds__(256, 2)
void k_energy(const float* __restrict__ enc) {
    __shared__ float sE[32];           // 8 warps * 4 rows

    const int tid  = threadIdx.x;
    const int wid  = tid >> 5;         // 0..7
    const int lane = tid & 31;

    // Cache u in registers (one pass; L2-hot after k_compute_u).
    const float4* uv = reinterpret_cast<const float4*>(g_u);
    float4 u[16];
#pragma unroll
    for (int k = 0; k < 16; ++k)
        u[k] = uv[lane + k * 32];

    const int s0 = (blockIdx.x * 8 + wid) * RPW;

#pragma unroll
    for (int r = 0; r < RPW; ++r) {
        const int s = s0 + r;
        const float4* row = reinterpret_cast<const float4*>(enc + (size_t)s * H);
        float acc = 0.0f;
#pragma unroll
        for (int k = 0; k < 16; ++k) {
            float4 v = row[lane + k * 32];
            acc = fmaf(v.x, u[k].x, acc);
            acc = fmaf(v.y, u[k].y, acc);
            acc = fmaf(v.z, u[k].z, acc);
            acc = fmaf(v.w, u[k].w, acc);
        }
#pragma unroll
        for (int off = 16; off; off >>= 1)
            acc += __shfl_xor_sync(0xFFFFFFFFu, acc, off);
        if (lane == 0) {
            g_energy[s] = acc;
            sE[wid * RPW + r] = acc;
        }
    }
    __syncthreads();

    // Block-local (m, z) over 32 energies (warp 0).
    if (wid == 0) {
        float e = sE[lane];
        float m = e;
#pragma unroll
        for (int off = 16; off; off >>= 1)
            m = fmaxf(m, __shfl_xor_sync(0xFFFFFFFFu, m, off));
        float z = __expf(e - m);
#pragma unroll
        for (int off = 16; off; off >>= 1)
            z += __shfl_xor_sync(0xFFFFFFFFu, z, off);
        if (lane == 0) { g_mb[blockIdx.x] = m; g_zb[blockIdx.x] = z; }
    }
}

// ---------------------------------------------------------------------------
// Kernel 3: finalize. 32 blocks x 256 threads. Every block redundantly
// reduces the 256 (m,z) pairs (L2-hot) to (M, 1/Z), then normalizes its own
// 256-row output slice. Blocks 0..7 also re-zero g_u.
// ---------------------------------------------------------------------------
__global__ void k_finalize(float* __restrict__ out) {
    __shared__ float red[8];
    __shared__ float sM, sInvZ;

    const int tid  = threadIdx.x;     // 0..255
    const int lane = tid & 31;
    const int wid  = tid >> 5;        // 0..7

    const float m0 = g_mb[tid];
    const float z0 = g_zb[tid];

    // ---- block max ----
    float m = m0;
#pragma unroll
    for (int off = 16; off; off >>= 1)
        m = fmaxf(m, __shfl_xor_sync(0xFFFFFFFFu, m, off));
    if (lane == 0) red[wid] = m;
    __syncthreads();
    if (tid < 8) {
        float v = red[tid];
#pragma unroll
        for (int off = 4; off; off >>= 1)
            v = fmaxf(v, __shfl_xor_sync(0xFFu, v, off));
        if (tid == 0) sM = v;
    }
    __syncthreads();
    const float M = sM;

    // ---- block sum of z_i * exp(m_i - M) ----
    float z = z0 * __expf(m0 - M);
#pragma unroll
    for (int off = 16; off; off >>= 1)
        z += __shfl_xor_sync(0xFFFFFFFFu, z, off);
    if (lane == 0) red[wid] = z;
    __syncthreads();
    if (tid < 8) {
        float v = red[tid];
#pragma unroll
        for (int off = 4; off; off >>= 1)
            v += __shfl_xor_sync(0xFFu, v, off);
        if (tid == 0) sInvZ = 1.0f / v;
    }
    __syncthreads();
    const float invZ = sInvZ;

    // ---- normalize this block's slice ----
    const int s = blockIdx.x * 256 + tid;
    out[s] = __expf(g_energy[s] - M) * invZ;

    // ---- restore g_u == 0 invariant for the next invocation ----
    if (blockIdx.x < 8)
        g_u[blockIdx.x * 256 + tid] = 0.0f;
}

// ---------------------------------------------------------------------------
// Launch. Inputs: hidden[2048], encoder_outputs[8192*2048], W[2048*2048],
// b[2048] (zero + softmax-invariant -> ignored). Output: 8192 floats.
// ---------------------------------------------------------------------------
extern "C" void kernel_launch(void* const* d_in, const int* in_sizes, int n_in,
                              void* d_out, int out_size) {
    const float* hidden = (const float*)d_in[0];
    const float* enc    = (const float*)d_in[1];
    const float* W      = (const float*)d_in[2];
    float* out          = (float*)d_out;

    dim3 g1(H / 256, ICHUNKS);   // (8, 128)
    k_compute_u<<<g1, 256>>>(hidden, W);

    k_energy<<<256, 256>>>(enc);

    k_finalize<<<S / 256, 256>>>(out);
}

// round 10
// speedup vs baseline: 1.4190x; 1.0173x over previous
#include <cuda_runtime.h>

#define H 2048
#define S 8192
#define EB 256               // k_energy blocks (all resident: 2/SM on 148+ SMs)

// Scratch (no allocs allowed). g_u starts zero (static init); k_energy
// re-zeros it each invocation after the grid barrier, so "g_u == 0 on entry"
// holds for the correctness run, the capture, and every graph replay.
__device__ float    g_u[H];
__device__ float    g_mb[EB];
__device__ float    g_zb[EB];
__device__ unsigned g_count = 0;   // barrier arrival counter (self-resetting)
__device__ unsigned g_gen   = 0;   // barrier generation (monotonic across replays)

// ---------------------------------------------------------------------------
// Kernel 1: u[j] += sum over a 16-row i-chunk of h[i] * W[i, j]
// Grid (H/256, 128) = 1024 blocks (~7/SM). Fully unrolled 16-row loop,
// scalar coalesced loads -> maximal chip-wide loads in flight. (Proven R9.)
// ---------------------------------------------------------------------------
#define ICHUNKS 128
#define IROWS   (H / ICHUNKS)     // 16

__global__ void k_compute_u(const float* __restrict__ h,
                            const float* __restrict__ W) {
    const int j  = blockIdx.x * blockDim.x + threadIdx.x;
    const int i0 = blockIdx.y * IROWS;

    float acc = 0.0f;
#pragma unroll
    for (int r = 0; r < IROWS; ++r) {
        const int i = i0 + r;
        acc = fmaf(__ldg(h + i), W[(size_t)i * H + j], acc);
    }
    atomicAdd(&g_u[j], acc);
}

// ---------------------------------------------------------------------------
// Grid barrier across EB blocks (all resident). Monotonic generation counter
// -> graph-replay safe. Both sides of the barrier are perfectly balanced
// (identical per-block work), so spin time is minimal.
// ---------------------------------------------------------------------------
__device__ __forceinline__ void grid_barrier() {
    __syncthreads();
    __threadfence();
    if (threadIdx.x == 0) {
        unsigned gen0 = *(volatile unsigned*)&g_gen;
        if (atomicAdd(&g_count, 1u) == EB - 1) {
            g_count = 0;
            __threadfence();
            atomicAdd(&g_gen, 1u);         // release
        } else {
            while (*(volatile unsigned*)&g_gen == gen0) { }
        }
        __threadfence();                   // acquire
    }
    __syncthreads();
}

// ---------------------------------------------------------------------------
// Kernel 2: energies + softmax, fused via one balanced grid barrier.
// Phase A (R9-proven): u register-resident per warp (lane caches u4[lane+32k],
// 64 regs); each warp streams 4 enc rows (16 independent LDG.128 per row);
// energies land in smem; block emits (m_b, z_b).
// Barrier. Phase B: every block redundantly reduces the 256 (m,z) pairs
// (1KB more, L2-hot) to (M, 1/Z) and normalizes its OWN 32 energies straight
// from smem to out. Blocks 0..7 re-zero g_u (read-before-barrier => safe).
// ---------------------------------------------------------------------------
#define RPW 4

__global__ __launch_bounds__(256, 2)
void k_energy(const float* __restrict__ enc, float* __restrict__ out) {
    __shared__ float sE[32];           // 8 warps * 4 rows
    __shared__ float red[8];
    __shared__ float sM, sInvZ;

    const int tid  = threadIdx.x;
    const int wid  = tid >> 5;         // 0..7
    const int lane = tid & 31;

    // ---- Phase A: cache u in registers (L2-hot after k_compute_u) ----
    const float4* uv = reinterpret_cast<const float4*>(g_u);
    float4 u[16];
#pragma unroll
    for (int k = 0; k < 16; ++k)
        u[k] = uv[lane + k * 32];

    const int s0 = (blockIdx.x * 8 + wid) * RPW;

#pragma unroll
    for (int r = 0; r < RPW; ++r) {
        const float4* row =
            reinterpret_cast<const float4*>(enc + (size_t)(s0 + r) * H);
        float acc = 0.0f;
#pragma unroll
        for (int k = 0; k < 16; ++k) {
            float4 v = row[lane + k * 32];
            acc = fmaf(v.x, u[k].x, acc);
            acc = fmaf(v.y, u[k].y, acc);
            acc = fmaf(v.z, u[k].z, acc);
            acc = fmaf(v.w, u[k].w, acc);
        }
#pragma unroll
        for (int off = 16; off; off >>= 1)
            acc += __shfl_xor_sync(0xFFFFFFFFu, acc, off);
        if (lane == 0) sE[wid * RPW + r] = acc;
    }
    __syncthreads();

    // Block-local (m, z) over this block's 32 energies (warp 0).
    if (wid == 0) {
        float e = sE[lane];
        float m = e;
#pragma unroll
        for (int off = 16; off; off >>= 1)
            m = fmaxf(m, __shfl_xor_sync(0xFFFFFFFFu, m, off));
        float z = __expf(e - m);
#pragma unroll
        for (int off = 16; off; off >>= 1)
            z += __shfl_xor_sync(0xFFFFFFFFu, z, off);
        if (lane == 0) { g_mb[blockIdx.x] = m; g_zb[blockIdx.x] = z; }
    }

    grid_barrier();   // all (m_b, z_b) visible; all u reads complete

    // ---- Phase B: global (M, 1/Z), redundant per block ----
    if (tid < 32) {
        float m = -1e30f;
#pragma unroll
        for (int i = 0; i < EB / 32; ++i)
            m = fmaxf(m, g_mb[lane + i * 32]);
#pragma unroll
        for (int off = 16; off; off >>= 1)
            m = fmaxf(m, __shfl_xor_sync(0xFFFFFFFFu, m, off));
        float z = 0.0f;
#pragma unroll
        for (int i = 0; i < EB / 32; ++i)
            z += g_zb[lane + i * 32] * __expf(g_mb[lane + i * 32] - m);
#pragma unroll
        for (int off = 16; off; off >>= 1)
            z += __shfl_xor_sync(0xFFFFFFFFu, z, off);
        if (lane == 0) { sM = m; sInvZ = 1.0f / z; }
    }
    __syncthreads();

    // Normalize this block's 32 energies (still in smem) -> out.
    if (tid < 32)
        out[blockIdx.x * 32 + tid] = __expf(sE[tid] - sM) * sInvZ;

    // Restore g_u == 0 invariant (u was consumed before the barrier).
    if (blockIdx.x < 8)
        g_u[blockIdx.x * 256 + tid] = 0.0f;
}

// ---------------------------------------------------------------------------
// Launch. Inputs: hidden[2048], encoder_outputs[8192*2048], W[2048*2048],
// b[2048] (zero + softmax-invariant -> ignored). Output: 8192 floats.
// ---------------------------------------------------------------------------
extern "C" void kernel_launch(void* const* d_in, const int* in_sizes, int n_in,
                              void* d_out, int out_size) {
    const float* hidden = (const float*)d_in[0];
    const float* enc    = (const float*)d_in[1];
    const float* W      = (const float*)d_in[2];
    float* out          = (float*)d_out;

    dim3 g1(H / 256, ICHUNKS);   // (8, 128) = 1024 blocks
    k_compute_u<<<g1, 256>>>(hidden, W);

    k_energy<<<EB, 256>>>(enc, out);
}